// round 2
// baseline (speedup 1.0000x reference)
#include <cuda_runtime.h>

// context_window: out[b, f*11 + c, t] = x[b, f, t + c - 5], zero-padded in t.
// x: (32, 80, 3000) fp32 -> out: (32, 880, 3000) fp32.
// Hardcoded per the reference setup: B=32, F=80, T=3000, L=R=5, C=11.
//
// R2: 8 time positions per thread (24-float register window, 6x LDG.128,
// 22x STG.128 streaming stores) to cut L1tex load wavefronts ~40%.

#define T_DIM   3000
#define C_LEN   11
#define ROWS    (32 * 80)     // 2560
#define T8      (T_DIM / 8)   // 375 eight-wide chunks per row

__global__ __launch_bounds__(128) void context_window_kernel(
    const float* __restrict__ x, float* __restrict__ out)
{
    int t8 = blockIdx.x * blockDim.x + threadIdx.x;
    if (t8 >= T8) return;
    int row = blockIdx.y;                 // b*80 + f
    int t = t8 * 8;

    const float* __restrict__ xr = x + row * T_DIM;

    // Register window covering x[t-8 .. t+15] (w[k] = x[t-8+k]).
    // out[c, t+j] = x[t + j + c - 5] = w[j + c + 3]; used range w[3..20].
    float w[24];

    if (t8 >= 1 && t8 < T8 - 1) {
        // Fast path: 6 aligned float4 loads, fully in-range (t-8 >= 0, t+15 <= 2999).
        const float4* __restrict__ p = reinterpret_cast<const float4*>(xr + t - 8);
        #pragma unroll
        for (int i = 0; i < 6; i++) {
            float4 v = p[i];
            w[4*i + 0] = v.x; w[4*i + 1] = v.y;
            w[4*i + 2] = v.z; w[4*i + 3] = v.w;
        }
    } else {
        // Edge path (t8 in {0, 374}): scalar bounds-checked loads.
        #pragma unroll
        for (int k = 0; k < 24; k++) {
            int idx = t - 8 + k;
            w[k] = (idx >= 0 && idx < T_DIM) ? xr[idx] : 0.0f;
        }
    }

    // 22 coalesced, aligned, streaming float4 stores — two per context shift.
    float* __restrict__ orow = out + (row * C_LEN) * T_DIM + t;
    #pragma unroll
    for (int c = 0; c < C_LEN; c++) {
        float4 a = make_float4(w[c + 3], w[c + 4], w[c + 5],  w[c + 6]);
        float4 b = make_float4(w[c + 7], w[c + 8], w[c + 9],  w[c + 10]);
        float4* dst = reinterpret_cast<float4*>(orow + c * T_DIM);
        __stcs(dst,     a);
        __stcs(dst + 1, b);
    }
}

extern "C" void kernel_launch(void* const* d_in, const int* in_sizes, int n_in,
                              void* d_out, int out_size)
{
    const float* x = (const float*)d_in[0];
    float* out = (float*)d_out;

    dim3 block(128);
    dim3 grid((T8 + 127) / 128, ROWS);   // (3, 2560)
    context_window_kernel<<<grid, block>>>(x, out);
}

// round 3
// speedup vs baseline: 1.7116x; 1.7116x over previous
#include <cuda_runtime.h>

// context_window: out[b, f*11 + c, t] = x[b, f, t + c - 5], zero-padded in t.
// x: (32, 80, 3000) fp32 -> out: (32, 880, 3000) fp32.
// Hardcoded per the reference setup: B=32, F=80, T=3000, L=R=5, C=11.
//
// R3: R1 layout (4 time positions/thread -> contiguous 512B warp stores,
// proven 55.3us @ DRAM 70.9%) + streaming store hint (st.global.cs) so the
// write-once output stream is evict-first in L2 and the 11x-reused input
// stays L2-resident.

#define T_DIM   3000
#define C_LEN   11
#define ROWS    (32 * 80)     // B*F = 2560
#define T4      (T_DIM / 4)   // 750 float4 chunks per row

__device__ __forceinline__ void stg_cs(float4* p, float4 v) {
    asm volatile("st.global.cs.v4.f32 [%0], {%1, %2, %3, %4};"
                 :: "l"(p), "f"(v.x), "f"(v.y), "f"(v.z), "f"(v.w)
                 : "memory");
}

__global__ __launch_bounds__(256) void context_window_kernel(
    const float* __restrict__ x, float* __restrict__ out)
{
    int t4 = blockIdx.x * blockDim.x + threadIdx.x;
    if (t4 >= T4) return;
    int row = blockIdx.y;                 // b*80 + f
    int t = t4 * 4;

    const float* __restrict__ xr = x + row * T_DIM;

    // Register window covering x[t-8 .. t+11] (w[k] = x[t-8+k]).
    // out[c, t+j] = x[t + j + c - 5] = w[j + c + 3]; used range w[3..16].
    float w[20];

    if (t4 >= 2 && t4 <= T4 - 3) {
        // Fast path: 5 aligned float4 loads, fully in-range.
        const float4* __restrict__ p = reinterpret_cast<const float4*>(xr + t - 8);
        #pragma unroll
        for (int i = 0; i < 5; i++) {
            float4 v = p[i];
            w[4*i + 0] = v.x; w[4*i + 1] = v.y;
            w[4*i + 2] = v.z; w[4*i + 3] = v.w;
        }
    } else {
        // Edge path (t4 in {0,1,748,749}): scalar bounds-checked loads.
        #pragma unroll
        for (int k = 0; k < 20; k++) {
            int idx = t - 8 + k;
            w[k] = (idx >= 0 && idx < T_DIM) ? xr[idx] : 0.0f;
        }
    }

    // 11 coalesced, aligned float4 streaming stores — one per context shift.
    // Warp-wide each store is 512B fully contiguous.
    float* __restrict__ orow = out + (row * C_LEN) * T_DIM + t;
    #pragma unroll
    for (int c = 0; c < C_LEN; c++) {
        float4 v = make_float4(w[c + 3], w[c + 4], w[c + 5], w[c + 6]);
        stg_cs(reinterpret_cast<float4*>(orow + c * T_DIM), v);
    }
}

extern "C" void kernel_launch(void* const* d_in, const int* in_sizes, int n_in,
                              void* d_out, int out_size)
{
    const float* x = (const float*)d_in[0];
    float* out = (float*)d_out;

    dim3 block(256);
    dim3 grid((T4 + 255) / 256, ROWS);   // (3, 2560)
    context_window_kernel<<<grid, block>>>(x, out);
}

// round 4
// speedup vs baseline: 1.7156x; 1.0023x over previous
#include <cuda_runtime.h>

// context_window: out[b, f*11 + c, t] = x[b, f, t + c - 5], zero-padded in t.
// x: (32, 80, 3000) fp32 -> out: (32, 880, 3000) fp32.
//
// R4: each lane loads ONE aligned float4 (warp-wide 512B, 128B-aligned -> 4 L1
// wavefronts) and assembles its 14-float context window [t-5, t+9) via warp
// shuffles from neighbor lanes. Kills the 4.4x L1 load-wavefront amplification
// of the 5-overlapping-LDG scheme. Stores unchanged (11x STG.128, warp-wide
// 512B contiguous, streaming hint).

#define T_DIM   3000
#define C_LEN   11
#define ROWS    (32 * 80)     // 2560
#define T4      (T_DIM / 4)   // 750
#define FULL    0xffffffffu

__device__ __forceinline__ void stg_cs(float* p, float4 v) {
    asm volatile("st.global.cs.v4.f32 [%0], {%1, %2, %3, %4};"
                 :: "l"(p), "f"(v.x), "f"(v.y), "f"(v.z), "f"(v.w)
                 : "memory");
}

__device__ __forceinline__ float ld_safe(const float* __restrict__ xr, int idx) {
    return (idx >= 0 && idx < T_DIM) ? __ldg(xr + idx) : 0.0f;
}

__global__ __launch_bounds__(256) void context_window_kernel(
    const float* __restrict__ x, float* __restrict__ out)
{
    int t4   = blockIdx.x * blockDim.x + threadIdx.x;
    int row  = blockIdx.y;                 // b*80 + f
    int lane = threadIdx.x & 31;
    int t    = t4 * 4;

    const float* __restrict__ xr = x + row * T_DIM;

    // Own aligned float4: x[t .. t+3]. Inactive lanes (t4 >= 750) carry zeros,
    // which is exactly the zero-padding their neighbors need via shuffle.
    bool active = (t4 < T4);
    float4 own = make_float4(0.f, 0.f, 0.f, 0.f);
    if (active)
        own = *reinterpret_cast<const float4*>(xr + t);

    // Window w[k] = x[t - 5 + k], k = 0..13 (covers all 11 shifts of 4 outputs).
    //   w[0]     <- lane-2 own.w   (x[t-5])
    //   w[1..4]  <- lane-1 own     (x[t-4..t-1])
    //   w[5..8]  <- own
    //   w[9..12] <- lane+1 own     (x[t+4..t+7])
    //   w[13]    <- lane+2 own.x   (x[t+8])
    float4 up1, dn1;
    up1.x = __shfl_up_sync(FULL, own.x, 1);
    up1.y = __shfl_up_sync(FULL, own.y, 1);
    up1.z = __shfl_up_sync(FULL, own.z, 1);
    up1.w = __shfl_up_sync(FULL, own.w, 1);
    dn1.x = __shfl_down_sync(FULL, own.x, 1);
    dn1.y = __shfl_down_sync(FULL, own.y, 1);
    dn1.z = __shfl_down_sync(FULL, own.z, 1);
    dn1.w = __shfl_down_sync(FULL, own.w, 1);
    float w0  = __shfl_up_sync(FULL, own.w, 2);    // x[t-5]
    float w13 = __shfl_down_sync(FULL, own.x, 2);  // x[t+8]

    // Cross-warp-boundary fixups (also provide zero padding at row edges).
    if (lane == 0) {
        w0 = ld_safe(xr, t - 5);
        up1 = make_float4(ld_safe(xr, t - 4), ld_safe(xr, t - 3),
                          ld_safe(xr, t - 2), ld_safe(xr, t - 1));
    } else if (lane == 1) {
        w0 = ld_safe(xr, t - 5);
    }
    if (lane == 31) {
        dn1 = make_float4(ld_safe(xr, t + 4), ld_safe(xr, t + 5),
                          ld_safe(xr, t + 6), ld_safe(xr, t + 7));
        w13 = ld_safe(xr, t + 8);
    } else if (lane == 30) {
        w13 = ld_safe(xr, t + 8);
    }

    if (!active) return;

    float w[14] = { w0,
                    up1.x, up1.y, up1.z, up1.w,
                    own.x, own.y, own.z, own.w,
                    dn1.x, dn1.y, dn1.z, dn1.w,
                    w13 };

    // 11 coalesced, aligned float4 streaming stores (warp-wide 512B each).
    float* __restrict__ orow = out + (row * C_LEN) * T_DIM + t;
    #pragma unroll
    for (int c = 0; c < C_LEN; c++) {
        stg_cs(orow + c * T_DIM, make_float4(w[c], w[c+1], w[c+2], w[c+3]));
    }
}

extern "C" void kernel_launch(void* const* d_in, const int* in_sizes, int n_in,
                              void* d_out, int out_size)
{
    const float* x = (const float*)d_in[0];
    float* out = (float*)d_out;

    dim3 block(256);
    dim3 grid((T4 + 255) / 256, ROWS);   // (3, 2560)
    context_window_kernel<<<grid, block>>>(x, out);
}